// round 14
// baseline (speedup 1.0000x reference)
#include <cuda_runtime.h>
#include <cuda_bf16.h>
#include <cuda_fp16.h>
#include <cstdint>

#define BATCH 2
#define CH 64
#define DI 32
#define NP 6400
#define SPL 50
#define QTCH 100               // 64-key chunks per batch (g_Vz stride)
#define TPI 2                  // tiles per item (128 keys)
#define IPB 2500               // items per batch = 50 qtiles * 50 splits
#define ITEMS 5000
#define LOG2E 1.4426950408889634f

typedef uint32_t u32;
typedef unsigned long long u64;

// ---------------- scratch ----------------
__device__ uint4 g_Qh[BATCH * NP * 4];   // fp16 q hi
__device__ uint4 g_Ql[BATCH * NP * 4];   // fp16 q lo residual
__device__ uint4 g_Kz[BATCH * NP * 4];   // fp16 k single, t4-blocked
__device__ uint4 g_Vz[BATCH * DI * QTCH * 16];  // bf16 hi/lo V^T blocks
__device__ float g_thn[BATCH * NP];
__device__ unsigned g_phimax[BATCH];
__device__ unsigned g_ctr;
__device__ unsigned g_scnt[BATCH * 50];  // per-(b,qt) completion counters
__device__ float g_acc[BATCH * SPL * NP * DI];
__device__ float g_lp[BATCH * SPL * NP];

// ---------------- helpers ----------------
__device__ __forceinline__ u64 f2fma(u64 a, u64 b, u64 c) {
    u64 d; asm("fma.rn.f32x2 %0,%1,%2,%3;" : "=l"(d) : "l"(a), "l"(b), "l"(c)); return d;
}
__device__ __forceinline__ u64 f2add(u64 a, u64 b) {
    u64 d; asm("add.rn.f32x2 %0,%1,%2;" : "=l"(d) : "l"(a), "l"(b)); return d;
}
__device__ __forceinline__ float f2hadd(u64 a) {
    float lo, hi; asm("mov.b64 {%0,%1},%2;" : "=f"(lo), "=f"(hi) : "l"(a)); return lo + hi;
}
__device__ __forceinline__ u32 pkbf(float hi, float lo) {
    u32 r; asm("cvt.rn.bf16x2.f32 %0,%1,%2;" : "=r"(r) : "f"(hi), "f"(lo)); return r;
}
__device__ __forceinline__ u32 pkf16(float hi, float lo) {
    u32 r; asm("cvt.rn.f16x2.f32 %0,%1,%2;" : "=r"(r) : "f"(hi), "f"(lo)); return r;
}
__device__ __forceinline__ float f16lo(u32 p) {
    __half_raw hr; hr.x = (unsigned short)(p & 0xffffu); return __half2float(__half(hr));
}
__device__ __forceinline__ float f16hi(u32 p) {
    __half_raw hr; hr.x = (unsigned short)(p >> 16); return __half2float(__half(hr));
}
__device__ __forceinline__ float bflo(u32 p) { return __uint_as_float(p << 16); }
__device__ __forceinline__ float bfhi(u32 p) { return __uint_as_float(p & 0xffff0000u); }
__device__ __forceinline__ float ex2f(float x) {
    float r; asm("ex2.approx.f32 %0,%1;" : "=f"(r) : "f"(x)); return r;
}
__device__ __forceinline__ void mma_bf16(float* c, const u32* a, u32 b0, u32 b1) {
    asm("mma.sync.aligned.m16n8k16.row.col.f32.bf16.bf16.f32 "
        "{%0,%1,%2,%3},{%4,%5,%6,%7},{%8,%9},{%0,%1,%2,%3};"
        : "+f"(c[0]), "+f"(c[1]), "+f"(c[2]), "+f"(c[3])
        : "r"(a[0]), "r"(a[1]), "r"(a[2]), "r"(a[3]), "r"(b0), "r"(b1));
}
__device__ __forceinline__ void mma_f16(float* c, const u32* a, u32 b0, u32 b1) {
    asm("mma.sync.aligned.m16n8k16.row.col.f32.f16.f16.f32 "
        "{%0,%1,%2,%3},{%4,%5,%6,%7},{%8,%9},{%0,%1,%2,%3};"
        : "+f"(c[0]), "+f"(c[1]), "+f"(c[2]), "+f"(c[3])
        : "r"(a[0]), "r"(a[1]), "r"(a[2]), "r"(a[3]), "r"(b0), "r"(b1));
}
__device__ __forceinline__ void cpa16(u32 sa, const void* g) {
    asm volatile("cp.async.cg.shared.global [%0],[%1],16;" :: "r"(sa), "l"(g) : "memory");
}
__device__ __forceinline__ u32 smaddr(const void* p) {
    u32 a; asm("{ .reg .u64 t; cvta.to.shared.u64 t,%1; cvt.u32.u64 %0,t; }" : "=r"(a) : "l"(p));
    return a;
}

// ---------------------------------------------------------------------------
// Stage 1: projection (unchanged from R13). grid (100, 3, 2), 128 threads.
// ---------------------------------------------------------------------------
#define PQ 64
__global__ void __launch_bounds__(128) proj_kernel(
    const float* __restrict__ x,
    const float* __restrict__ theta_w,
    const float* __restrict__ phi_w,
    const float* __restrict__ gw)
{
    __shared__ __align__(16) float xs[CH * PQ];
    __shared__ __align__(16) float wT[CH * DI];

    const int b = blockIdx.z, m = blockIdx.y, n0 = blockIdx.x * PQ;
    const int tid = threadIdx.x;
    const int p = tid >> 1, h = tid & 1;
    const float* wsrc = (m == 0) ? theta_w : (m == 1) ? phi_w : gw;

    for (int idx = tid; idx < DI * CH; idx += 128) {
        int i = idx >> 6, c = idx & 63;
        wT[c * DI + i] = wsrc[idx];
    }
    const float* xb = x + b * CH * NP + n0;
    #pragma unroll
    for (int i = 0; i < 32; i++) {
        int idx = tid + 128 * i;
        xs[idx] = xb[(idx >> 6) * NP + (idx & 63)];
    }
    __syncthreads();

    u64 acc2[8];
    #pragma unroll
    for (int i = 0; i < 8; i++) acc2[i] = 0ull;
    #pragma unroll 4
    for (int c = 0; c < CH; c++) {
        float xv = xs[c * PQ + p];
        u64 x2; asm("mov.b64 %0,{%1,%1};" : "=l"(x2) : "f"(xv));
        const ulonglong2* w2 = (const ulonglong2*)(wT + c * DI + 16 * h);
        #pragma unroll
        for (int i4 = 0; i4 < 4; i4++) {
            ulonglong2 ww = w2[i4];
            acc2[2 * i4]     = f2fma(ww.x, x2, acc2[2 * i4]);
            acc2[2 * i4 + 1] = f2fma(ww.y, x2, acc2[2 * i4 + 1]);
        }
    }
    float v[16];
    #pragma unroll
    for (int i2 = 0; i2 < 8; i2++)
        asm("mov.b64 {%0,%1},%2;" : "=f"(v[2 * i2]), "=f"(v[2 * i2 + 1]) : "l"(acc2[i2]));

    const int n = n0 + p;
    if (m == 0) {
        #pragma unroll
        for (int i = 0; i < 16; i++) v[i] *= LOG2E;
        float nrm = 0.f;
        u32 hw[8], lw[8];
        #pragma unroll
        for (int i2 = 0; i2 < 8; i2++) {
            float f0 = v[2 * i2], f1 = v[2 * i2 + 1];
            nrm = fmaf(f0, f0, fmaf(f1, f1, nrm));
            u32 hh = pkf16(f1, f0);
            hw[i2] = hh;
            lw[i2] = pkf16(f1 - f16hi(hh), f0 - f16lo(hh));
        }
        nrm += __shfl_xor_sync(0xffffffffu, nrm, 1);
        uint4* hp = g_Qh + (b * NP + n) * 4 + 2 * h;
        uint4* lp = g_Ql + (b * NP + n) * 4 + 2 * h;
        hp[0] = make_uint4(hw[0], hw[1], hw[2], hw[3]);
        hp[1] = make_uint4(hw[4], hw[5], hw[6], hw[7]);
        lp[0] = make_uint4(lw[0], lw[1], lw[2], lw[3]);
        lp[1] = make_uint4(lw[4], lw[5], lw[6], lw[7]);
        if (h == 0) g_thn[b * NP + n] = nrm;
    } else if (m == 1) {
        float nrm = 0.f;
        u32 kw[8];
        #pragma unroll
        for (int i2 = 0; i2 < 8; i2++) {
            float f0 = v[2 * i2], f1 = v[2 * i2 + 1];
            nrm = fmaf(f0, f0, fmaf(f1, f1, nrm));
            kw[i2] = pkf16(f1, f0);
        }
        nrm += __shfl_xor_sync(0xffffffffu, nrm, 1);
        u32 ok[8];
        #pragma unroll
        for (int t = 0; t < 8; t++)
            ok[t] = __shfl_xor_sync(0xffffffffu, kw[t], 1);
        uint4* dst = g_Kz + (b * NP + n) * 4;
        if (h == 0) {
            dst[0] = make_uint4(kw[0], kw[4], ok[0], ok[4]);
            dst[1] = make_uint4(kw[1], kw[5], ok[1], ok[5]);
        } else {
            dst[2] = make_uint4(ok[2], ok[6], kw[2], kw[6]);
            dst[3] = make_uint4(ok[3], ok[7], kw[3], kw[7]);
        }
        unsigned mx = __reduce_max_sync(0xffffffffu, __float_as_uint(nrm));
        if ((tid & 31) == 0) atomicMax(&g_phimax[b], mx);
    } else {
        __syncthreads();
        u32* vh = (u32*)xs;
        u32* vl = vh + 32 * 32;
        __nv_bfloat16* vhb = (__nv_bfloat16*)vh;
        __nv_bfloat16* vlb = (__nv_bfloat16*)vl;
        #pragma unroll
        for (int i = 0; i < 16; i++) {
            int d = 16 * h + i;
            __nv_bfloat16 hh = __float2bfloat16(v[i]);
            vhb[d * PQ + p] = hh;
            vlb[d * PQ + p] = __float2bfloat16(v[i] - __bfloat162float(hh));
        }
        __syncthreads();
        #pragma unroll
        for (int i = 0; i < 4; i++) {
            int idx = tid + 128 * i;
            int d = idx >> 4, rem = idx & 15;
            int s4 = rem >> 2, t4 = rem & 3;
            int kp = 8 * s4 + t4;
            uint4 val = make_uint4(vh[d * 32 + kp], vh[d * 32 + kp + 4],
                                   vl[d * 32 + kp], vl[d * 32 + kp + 4]);
            int blk = ((s4 ^ (d & 1)) << 2) + t4;
            g_Vz[((b * DI + d) * QTCH + blockIdx.x) * 16 + blk] = val;
        }
    }
}

// ---------------------------------------------------------------------------
// Stage 2: persistent flash attention + FUSED split-K merge (last-CTA pattern).
// QK = fp16 2-term (32 MMA), PV = bf16 2-term (32 MMA). SPL=50, TPI=2,
// ITEMS=5000 over 296 CTAs -> scheduling tail < 6%.
// smem: KV 2x12KB + Q 16KB + w_w 8KB + ctrl.
// ---------------------------------------------------------------------------
#define KBUF 12288
#define VOFF 4096
#define QOFF 24576
#define WOFF 40960
#define SMN  49152
#define ASMEM 49168

__global__ void __launch_bounds__(256, 2) attn_kernel(
    const float* __restrict__ x,
    const float* __restrict__ w_w,
    float* __restrict__ out)
{
    extern __shared__ __align__(16) char smem[];
    const int tid = threadIdx.x, w = tid >> 5, lane = tid & 31;
    const int g = lane >> 2, t4 = lane & 3;
    const int gp = g & 1;
    const u32 smbase = smaddr(smem);
    volatile u32* sm_next = (volatile u32*)(smem + SMN);
    volatile u32* sm_flag = (volatile u32*)(smem + SMN + 4);
    float* ws = (float*)(smem + WOFF);

    auto prefetchKV = [&](int b, int k0, int buf) {
        const u32 bb = smbase + buf * KBUF;
        const uint4* ks = g_Kz + (b * NP + k0) * 4;           // 256 uint4
        const uint4* vs = g_Vz + (b * DI * QTCH + (k0 >> 6)) * 16;
        cpa16(bb + tid * 16, ks + tid);
        #pragma unroll
        for (int i = 0; i < 2; i++) {
            int idx = tid + 256 * i;
            int d = idx >> 4, blk = idx & 15;
            cpa16(bb + VOFF + idx * 16, vs + d * QTCH * 16 + blk);
        }
    };
    auto prefetchQ = [&](int b, int n0) {
        const uint4* qh = g_Qh + (b * NP + n0) * 4;           // 512 uint4
        const uint4* ql = g_Ql + (b * NP + n0) * 4;
        #pragma unroll
        for (int i = 0; i < 2; i++) {
            int idx = tid + 256 * i;
            cpa16(smbase + QOFF + idx * 16, qh + idx);
            cpa16(smbase + QOFF + 8192 + idx * 16, ql + idx);
        }
    };

    // stage w_w into persistent smem (for fused merge epilogue)
    #pragma unroll
    for (int i = 0; i < 8; i++) ws[tid + 256 * i] = w_w[tid + 256 * i];

    if (tid == 0) *sm_next = atomicAdd(&g_ctr, 1u);
    __syncthreads();
    unsigned wi = *sm_next;
    if (wi < ITEMS) {
        int b = wi / IPB, r = wi % IPB;
        prefetchKV(b, (r % SPL) * 128, 0);
        prefetchQ(b, (r / SPL) * 128);
        asm volatile("cp.async.commit_group;" ::: "memory");
    }
    int tc = 0;

    while (wi < ITEMS) {
        const int b = wi / IPB;
        const int r = wi % IPB;
        const int qt = r / SPL, sp = r % SPL;
        const int n0 = qt * 128, k0s = sp * 128;
        const int lr0 = w * 16 + g;
        const int q0 = n0 + lr0, q1 = q0 + 8;

        const float pm = sqrtf(__uint_as_float(g_phimax[b]));
        const float bd0 = sqrtf(g_thn[b * NP + q0]) * pm;
        const float bd1 = sqrtf(g_thn[b * NP + q1]) * pm;

        float o[4][4];
        #pragma unroll
        for (int i = 0; i < 4; i++)
            #pragma unroll
            for (int j = 0; j < 4; j++) o[i][j] = 0.f;
        float l0 = 0.f, l1 = 0.f;
        u32 ah[2][4], al[2][4];
        unsigned nwi = ITEMS;

        for (int t = 0; t < TPI; t++) {
            asm volatile("cp.async.wait_group 0;" ::: "memory");
            __syncthreads();

            if (t == 0) {
                const u32* qh32 = (const u32*)(smem + QOFF);
                const u32* ql32 = (const u32*)(smem + QOFF + 8192);
                const int r0 = lr0 * 16, r1 = (lr0 + 8) * 16;
                #pragma unroll
                for (int s = 0; s < 2; s++) {
                    ah[s][0] = qh32[r0 + t4 + 8 * s];
                    ah[s][1] = qh32[r1 + t4 + 8 * s];
                    ah[s][2] = qh32[r0 + t4 + 4 + 8 * s];
                    ah[s][3] = qh32[r1 + t4 + 4 + 8 * s];
                    al[s][0] = ql32[r0 + t4 + 8 * s];
                    al[s][1] = ql32[r1 + t4 + 8 * s];
                    al[s][2] = ql32[r0 + t4 + 4 + 8 * s];
                    al[s][3] = ql32[r1 + t4 + 4 + 8 * s];
                }
            }
            if (t == TPI - 2 && tid == 0) *sm_next = atomicAdd(&g_ctr, 1u);
            if (t < TPI - 1) {
                prefetchKV(b, k0s + (t + 1) * 64, (tc + 1) & 1);
                asm volatile("cp.async.commit_group;" ::: "memory");
            } else {
                nwi = *sm_next;
                if (nwi < ITEMS) {
                    int nb = nwi / IPB, nr = nwi % IPB;
                    prefetchKV(nb, (nr % SPL) * 128, (tc + 1) & 1);
                    prefetchQ(nb, (nr / SPL) * 128);
                    asm volatile("cp.async.commit_group;" ::: "memory");
                }
            }

            const char* bb = smem + (tc & 1) * KBUF;
            const char* vb0 = bb + VOFF;

            // ---- j-pair pipeline: QK(jp+1) | exp/pack(jp) | PV(jp) ----
            float sc[2][2][4];
            u32 ph[4];

            #define QK_PAIR(jp, scp)                                            \
                do {                                                            \
                    (scp)[0][0] = -bd0; (scp)[0][1] = -bd0;                     \
                    (scp)[0][2] = -bd1; (scp)[0][3] = -bd1;                     \
                    (scp)[1][0] = -bd0; (scp)[1][1] = -bd0;                     \
                    (scp)[1][2] = -bd1; (scp)[1][3] = -bd1;                     \
                    _Pragma("unroll")                                           \
                    for (int jj = 0; jj < 2; jj++) {                            \
                        int j = 2 * (jp) + jj;                                  \
                        uint4 kk = *(const uint4*)(bb + ((8 * j + g) << 6) + (t4 << 4)); \
                        mma_f16((scp)[jj], ah[0], kk.x, kk.y);                  \
                        mma_f16((scp)[jj], al[0], kk.x, kk.y);                  \
                        mma_f16((scp)[jj], ah[1], kk.z, kk.w);                  \
                        mma_f16((scp)[jj], al[1], kk.z, kk.w);                  \
                    }                                                           \
                } while (0)

            QK_PAIR(0, sc[0]);
            #pragma unroll
            for (int jp = 0; jp < 4; jp++) {
                if (jp < 3) QK_PAIR(jp + 1, sc[(jp + 1) & 1]);

                float* s0 = sc[jp & 1][0];
                float* s1 = sc[jp & 1][1];
                float p0 = ex2f(s0[0]), p1 = ex2f(s0[1]);
                float p2 = ex2f(s0[2]), p3 = ex2f(s0[3]);
                float p4 = ex2f(s1[0]), p5 = ex2f(s1[1]);
                float p6 = ex2f(s1[2]), p7 = ex2f(s1[3]);
                ph[0] = pkbf(p1, p0); ph[1] = pkbf(p3, p2);
                ph[2] = pkbf(p5, p4); ph[3] = pkbf(p7, p6);
                l0 += bflo(ph[0]) + bfhi(ph[0]) + bflo(ph[2]) + bfhi(ph[2]);
                l1 += bflo(ph[1]) + bfhi(ph[1]) + bflo(ph[3]) + bfhi(ph[3]);

                const int so4 = (((jp ^ gp) << 2) + t4) << 4;
                #pragma unroll
                for (int j2 = 0; j2 < 4; j2++) {
                    uint4 vv = *(const uint4*)(vb0 + ((8 * j2 + g) << 8) + so4);
                    mma_bf16(o[j2], ph, vv.x, vv.y);
                    mma_bf16(o[j2], ph, vv.z, vv.w);
                }
            }
            #undef QK_PAIR
            tc++;
        }

        l0 += __shfl_xor_sync(0xffffffffu, l0, 1);
        l0 += __shfl_xor_sync(0xffffffffu, l0, 2);
        l1 += __shfl_xor_sync(0xffffffffu, l1, 1);
        l1 += __shfl_xor_sync(0xffffffffu, l1, 2);

        const int pb = (b * SPL + sp) * NP;
        #pragma unroll
        for (int j2 = 0; j2 < 4; j2++) {
            *(float2*)(g_acc + (pb + q0) * DI + 8 * j2 + 2 * t4) = make_float2(o[j2][0], o[j2][1]);
            *(float2*)(g_acc + (pb + q1) * DI + 8 * j2 + 2 * t4) = make_float2(o[j2][2], o[j2][3]);
        }
        if (t4 == 0) { g_lp[pb + q0] = l0; g_lp[pb + q1] = l1; }

        // ---- fused merge: last CTA to finish a (b,qt) does projection ----
        __threadfence();
        __syncthreads();
        if (tid == 0) *sm_flag = atomicAdd(&g_scnt[b * 50 + qt], 1u);
        __syncthreads();
        if (*sm_flag == SPL - 1) {
            __threadfence();
            const int pos = tid & 127, hf = tid >> 7;
            const int n = n0 + pos;
            float l = 0.f;
            u64 y2[16];
            #pragma unroll
            for (int i = 0; i < 16; i++) y2[i] = 0ull;
            #pragma unroll 2
            for (int s = 0; s < SPL; s++) {
                l += g_lp[(b * SPL + s) * NP + n];
                const u64* ap = (const u64*)(g_acc + ((b * SPL + s) * NP + n) * DI);
                #pragma unroll
                for (int i2 = 0; i2 < 16; i2++) y2[i2] = f2add(y2[i2], ap[i2]);
            }
            const float inv = 1.f / l;
            u64 inv2; asm("mov.b64 %0,{%1,%1};" : "=l"(inv2) : "f"(inv));
            #pragma unroll
            for (int i2 = 0; i2 < 16; i2++) {
                u64 z = 0ull;
                y2[i2] = f2fma(y2[i2], inv2, z);
            }
            const float* xb = x + b * CH * NP + n;
            float* ob = out + b * CH * NP + n;
            const int c0 = hf * 32;
            #pragma unroll 2
            for (int c = c0; c < c0 + 32; c++) {
                const u64* w2 = (const u64*)(ws + c * DI);
                u64 o2 = 0ull;
                #pragma unroll
                for (int i2 = 0; i2 < 16; i2++) o2 = f2fma(w2[i2], y2[i2], o2);
                ob[c * NP] = xb[c * NP] + f2hadd(o2);
            }
        }

        wi = nwi;
    }
}

// ---------------------------------------------------------------------------
extern "C" void kernel_launch(void* const* d_in, const int* in_sizes, int n_in,
                              void* d_out, int out_size)
{
    const float* x       = (const float*)d_in[0];
    const float* gw      = (const float*)d_in[1];
    const float* theta_w = (const float*)d_in[2];
    const float* phi_w   = (const float*)d_in[3];
    const float* w_w     = (const float*)d_in[4];
    float* out           = (float*)d_out;

    void* pm = nullptr; cudaGetSymbolAddress(&pm, g_phimax);
    cudaMemsetAsync(pm, 0, sizeof(unsigned) * BATCH);
    void* pc = nullptr; cudaGetSymbolAddress(&pc, g_ctr);
    cudaMemsetAsync(pc, 0, sizeof(unsigned));
    void* ps = nullptr; cudaGetSymbolAddress(&ps, g_scnt);
    cudaMemsetAsync(ps, 0, sizeof(unsigned) * BATCH * 50);

    static int cfg = 0;
    if (!cfg) {
        cudaFuncSetAttribute(attn_kernel, cudaFuncAttributeMaxDynamicSharedMemorySize, ASMEM);
        cfg = 1;
    }

    dim3 gp(NP / PQ, 3, BATCH);
    proj_kernel<<<gp, 128>>>(x, theta_w, phi_w, gw);

    attn_kernel<<<296, 256, ASMEM>>>(x, w_w, out);
}

// round 15
// speedup vs baseline: 4.6968x; 4.6968x over previous
#include <cuda_runtime.h>
#include <cuda_bf16.h>
#include <cuda_fp16.h>
#include <cstdint>

#define BATCH 2
#define CH 64
#define DI 32
#define NP 6400
#define SPL 20
#define QTCH 100               // 64-key chunks per batch (g_Vz stride)
#define TPI 5                  // tiles per item (320 keys)
#define IPB 1000               // items per batch = 50 qtiles * 20 splits
#define ITEMS 2000
#define LOG2E 1.4426950408889634f

typedef uint32_t u32;
typedef unsigned long long u64;

// ---------------- scratch ----------------
__device__ uint4 g_Qh[BATCH * NP * 4];   // fp16 q hi
__device__ uint4 g_Ql[BATCH * NP * 4];   // fp16 q lo residual
__device__ uint4 g_Kz[BATCH * NP * 4];   // fp16 k single, t4-blocked
__device__ uint4 g_Vz[BATCH * DI * QTCH * 16];  // bf16 hi/lo V^T blocks
__device__ float g_thn[BATCH * NP];
__device__ unsigned g_phimax[BATCH];
__device__ unsigned g_ctr;
__device__ float g_acc[BATCH * SPL * NP * DI];
__device__ float g_lp[BATCH * SPL * NP];

// ---------------- helpers ----------------
__device__ __forceinline__ u64 f2fma(u64 a, u64 b, u64 c) {
    u64 d; asm("fma.rn.f32x2 %0,%1,%2,%3;" : "=l"(d) : "l"(a), "l"(b), "l"(c)); return d;
}
__device__ __forceinline__ u64 f2add(u64 a, u64 b) {
    u64 d; asm("add.rn.f32x2 %0,%1,%2;" : "=l"(d) : "l"(a), "l"(b)); return d;
}
__device__ __forceinline__ float f2hadd(u64 a) {
    float lo, hi; asm("mov.b64 {%0,%1},%2;" : "=f"(lo), "=f"(hi) : "l"(a)); return lo + hi;
}
__device__ __forceinline__ u32 pkbf(float hi, float lo) {
    u32 r; asm("cvt.rn.bf16x2.f32 %0,%1,%2;" : "=r"(r) : "f"(hi), "f"(lo)); return r;
}
__device__ __forceinline__ u32 pkf16(float hi, float lo) {
    u32 r; asm("cvt.rn.f16x2.f32 %0,%1,%2;" : "=r"(r) : "f"(hi), "f"(lo)); return r;
}
__device__ __forceinline__ float f16lo(u32 p) {
    __half_raw hr; hr.x = (unsigned short)(p & 0xffffu); return __half2float(__half(hr));
}
__device__ __forceinline__ float f16hi(u32 p) {
    __half_raw hr; hr.x = (unsigned short)(p >> 16); return __half2float(__half(hr));
}
__device__ __forceinline__ float bflo(u32 p) { return __uint_as_float(p << 16); }
__device__ __forceinline__ float bfhi(u32 p) { return __uint_as_float(p & 0xffff0000u); }
__device__ __forceinline__ float ex2f(float x) {
    float r; asm("ex2.approx.f32 %0,%1;" : "=f"(r) : "f"(x)); return r;
}
__device__ __forceinline__ void mma_bf16(float* c, const u32* a, u32 b0, u32 b1) {
    asm("mma.sync.aligned.m16n8k16.row.col.f32.bf16.bf16.f32 "
        "{%0,%1,%2,%3},{%4,%5,%6,%7},{%8,%9},{%0,%1,%2,%3};"
        : "+f"(c[0]), "+f"(c[1]), "+f"(c[2]), "+f"(c[3])
        : "r"(a[0]), "r"(a[1]), "r"(a[2]), "r"(a[3]), "r"(b0), "r"(b1));
}
__device__ __forceinline__ void mma_f16(float* c, const u32* a, u32 b0, u32 b1) {
    asm("mma.sync.aligned.m16n8k16.row.col.f32.f16.f16.f32 "
        "{%0,%1,%2,%3},{%4,%5,%6,%7},{%8,%9},{%0,%1,%2,%3};"
        : "+f"(c[0]), "+f"(c[1]), "+f"(c[2]), "+f"(c[3])
        : "r"(a[0]), "r"(a[1]), "r"(a[2]), "r"(a[3]), "r"(b0), "r"(b1));
}
__device__ __forceinline__ void cpa16(u32 sa, const void* g) {
    asm volatile("cp.async.cg.shared.global [%0],[%1],16;" :: "r"(sa), "l"(g) : "memory");
}
__device__ __forceinline__ u32 smaddr(const void* p) {
    u32 a; asm("{ .reg .u64 t; cvta.to.shared.u64 t,%1; cvt.u32.u64 %0,t; }" : "=r"(a) : "l"(p));
    return a;
}

// ---------------------------------------------------------------------------
// Stage 1: projection (R13, unchanged). grid (100, 3, 2), 128 threads.
// ---------------------------------------------------------------------------
#define PQ 64
__global__ void __launch_bounds__(128) proj_kernel(
    const float* __restrict__ x,
    const float* __restrict__ theta_w,
    const float* __restrict__ phi_w,
    const float* __restrict__ gw)
{
    __shared__ __align__(16) float xs[CH * PQ];
    __shared__ __align__(16) float wT[CH * DI];

    const int b = blockIdx.z, m = blockIdx.y, n0 = blockIdx.x * PQ;
    const int tid = threadIdx.x;
    const int p = tid >> 1, h = tid & 1;
    const float* wsrc = (m == 0) ? theta_w : (m == 1) ? phi_w : gw;

    for (int idx = tid; idx < DI * CH; idx += 128) {
        int i = idx >> 6, c = idx & 63;
        wT[c * DI + i] = wsrc[idx];
    }
    const float* xb = x + b * CH * NP + n0;
    #pragma unroll
    for (int i = 0; i < 32; i++) {
        int idx = tid + 128 * i;
        xs[idx] = xb[(idx >> 6) * NP + (idx & 63)];
    }
    __syncthreads();

    u64 acc2[8];
    #pragma unroll
    for (int i = 0; i < 8; i++) acc2[i] = 0ull;
    #pragma unroll 4
    for (int c = 0; c < CH; c++) {
        float xv = xs[c * PQ + p];
        u64 x2; asm("mov.b64 %0,{%1,%1};" : "=l"(x2) : "f"(xv));
        const ulonglong2* w2 = (const ulonglong2*)(wT + c * DI + 16 * h);
        #pragma unroll
        for (int i4 = 0; i4 < 4; i4++) {
            ulonglong2 ww = w2[i4];
            acc2[2 * i4]     = f2fma(ww.x, x2, acc2[2 * i4]);
            acc2[2 * i4 + 1] = f2fma(ww.y, x2, acc2[2 * i4 + 1]);
        }
    }
    float v[16];
    #pragma unroll
    for (int i2 = 0; i2 < 8; i2++)
        asm("mov.b64 {%0,%1},%2;" : "=f"(v[2 * i2]), "=f"(v[2 * i2 + 1]) : "l"(acc2[i2]));

    const int n = n0 + p;
    if (m == 0) {
        #pragma unroll
        for (int i = 0; i < 16; i++) v[i] *= LOG2E;
        float nrm = 0.f;
        u32 hw[8], lw[8];
        #pragma unroll
        for (int i2 = 0; i2 < 8; i2++) {
            float f0 = v[2 * i2], f1 = v[2 * i2 + 1];
            nrm = fmaf(f0, f0, fmaf(f1, f1, nrm));
            u32 hh = pkf16(f1, f0);
            hw[i2] = hh;
            lw[i2] = pkf16(f1 - f16hi(hh), f0 - f16lo(hh));
        }
        nrm += __shfl_xor_sync(0xffffffffu, nrm, 1);
        uint4* hp = g_Qh + (b * NP + n) * 4 + 2 * h;
        uint4* lp = g_Ql + (b * NP + n) * 4 + 2 * h;
        hp[0] = make_uint4(hw[0], hw[1], hw[2], hw[3]);
        hp[1] = make_uint4(hw[4], hw[5], hw[6], hw[7]);
        lp[0] = make_uint4(lw[0], lw[1], lw[2], lw[3]);
        lp[1] = make_uint4(lw[4], lw[5], lw[6], lw[7]);
        if (h == 0) g_thn[b * NP + n] = nrm;
    } else if (m == 1) {
        float nrm = 0.f;
        u32 kw[8];
        #pragma unroll
        for (int i2 = 0; i2 < 8; i2++) {
            float f0 = v[2 * i2], f1 = v[2 * i2 + 1];
            nrm = fmaf(f0, f0, fmaf(f1, f1, nrm));
            kw[i2] = pkf16(f1, f0);
        }
        nrm += __shfl_xor_sync(0xffffffffu, nrm, 1);
        u32 ok[8];
        #pragma unroll
        for (int t = 0; t < 8; t++)
            ok[t] = __shfl_xor_sync(0xffffffffu, kw[t], 1);
        uint4* dst = g_Kz + (b * NP + n) * 4;
        if (h == 0) {
            dst[0] = make_uint4(kw[0], kw[4], ok[0], ok[4]);
            dst[1] = make_uint4(kw[1], kw[5], ok[1], ok[5]);
        } else {
            dst[2] = make_uint4(ok[2], ok[6], kw[2], kw[6]);
            dst[3] = make_uint4(ok[3], ok[7], kw[3], kw[7]);
        }
        unsigned mx = __reduce_max_sync(0xffffffffu, __float_as_uint(nrm));
        if ((tid & 31) == 0) atomicMax(&g_phimax[b], mx);
    } else {
        __syncthreads();
        u32* vh = (u32*)xs;
        u32* vl = vh + 32 * 32;
        __nv_bfloat16* vhb = (__nv_bfloat16*)vh;
        __nv_bfloat16* vlb = (__nv_bfloat16*)vl;
        #pragma unroll
        for (int i = 0; i < 16; i++) {
            int d = 16 * h + i;
            __nv_bfloat16 hh = __float2bfloat16(v[i]);
            vhb[d * PQ + p] = hh;
            vlb[d * PQ + p] = __float2bfloat16(v[i] - __bfloat162float(hh));
        }
        __syncthreads();
        #pragma unroll
        for (int i = 0; i < 4; i++) {
            int idx = tid + 128 * i;
            int d = idx >> 4, rem = idx & 15;
            int s4 = rem >> 2, t4 = rem & 3;
            int kp = 8 * s4 + t4;
            uint4 val = make_uint4(vh[d * 32 + kp], vh[d * 32 + kp + 4],
                                   vl[d * 32 + kp], vl[d * 32 + kp + 4]);
            int blk = ((s4 ^ (d & 1)) << 2) + t4;
            g_Vz[((b * DI + d) * QTCH + blockIdx.x) * 16 + blk] = val;
        }
    }
}

// ---------------------------------------------------------------------------
// Stage 2: R13 attention, retuned scheduling: SPL=20, TPI=5, ITEMS=2000
// over 304 CTAs (~6.6 items/CTA -> steal tail ~8%). No in-loop fences.
// ---------------------------------------------------------------------------
#define KBUF 12288
#define VOFF 4096
#define QOFF 24576
#define SMN  40960
#define ASMEM 40976

__global__ void __launch_bounds__(256, 2) attn_kernel()
{
    extern __shared__ __align__(16) char smem[];
    const int tid = threadIdx.x, w = tid >> 5, lane = tid & 31;
    const int g = lane >> 2, t4 = lane & 3;
    const int gp = g & 1;
    const u32 smbase = smaddr(smem);
    volatile u32* sm_next = (volatile u32*)(smem + SMN);

    auto prefetchKV = [&](int b, int k0, int buf) {
        const u32 bb = smbase + buf * KBUF;
        const uint4* ks = g_Kz + (b * NP + k0) * 4;           // 256 uint4
        const uint4* vs = g_Vz + (b * DI * QTCH + (k0 >> 6)) * 16;
        cpa16(bb + tid * 16, ks + tid);
        #pragma unroll
        for (int i = 0; i < 2; i++) {
            int idx = tid + 256 * i;
            int d = idx >> 4, blk = idx & 15;
            cpa16(bb + VOFF + idx * 16, vs + d * QTCH * 16 + blk);
        }
    };
    auto prefetchQ = [&](int b, int n0) {
        const uint4* qh = g_Qh + (b * NP + n0) * 4;           // 512 uint4
        const uint4* ql = g_Ql + (b * NP + n0) * 4;
        #pragma unroll
        for (int i = 0; i < 2; i++) {
            int idx = tid + 256 * i;
            cpa16(smbase + QOFF + idx * 16, qh + idx);
            cpa16(smbase + QOFF + 8192 + idx * 16, ql + idx);
        }
    };

    if (tid == 0) *sm_next = atomicAdd(&g_ctr, 1u);
    __syncthreads();
    unsigned wi = *sm_next;
    if (wi < ITEMS) {
        int b = wi / IPB, r = wi % IPB;
        prefetchKV(b, (r % SPL) * 320, 0);
        prefetchQ(b, (r / SPL) * 128);
        asm volatile("cp.async.commit_group;" ::: "memory");
    }
    int tc = 0;

    while (wi < ITEMS) {
        const int b = wi / IPB;
        const int r = wi % IPB;
        const int qt = r / SPL, sp = r % SPL;
        const int n0 = qt * 128, k0s = sp * 320;
        const int lr0 = w * 16 + g;
        const int q0 = n0 + lr0, q1 = q0 + 8;

        const float pm = sqrtf(__uint_as_float(g_phimax[b]));
        const float bd0 = sqrtf(g_thn[b * NP + q0]) * pm;
        const float bd1 = sqrtf(g_thn[b * NP + q1]) * pm;

        float o[4][4];
        #pragma unroll
        for (int i = 0; i < 4; i++)
            #pragma unroll
            for (int j = 0; j < 4; j++) o[i][j] = 0.f;
        float l0 = 0.f, l1 = 0.f;
        u32 ah[2][4], al[2][4];
        unsigned nwi = ITEMS;

        for (int t = 0; t < TPI; t++) {
            asm volatile("cp.async.wait_group 0;" ::: "memory");
            __syncthreads();

            if (t == 0) {
                const u32* qh32 = (const u32*)(smem + QOFF);
                const u32* ql32 = (const u32*)(smem + QOFF + 8192);
                const int r0 = lr0 * 16, r1 = (lr0 + 8) * 16;
                #pragma unroll
                for (int s = 0; s < 2; s++) {
                    ah[s][0] = qh32[r0 + t4 + 8 * s];
                    ah[s][1] = qh32[r1 + t4 + 8 * s];
                    ah[s][2] = qh32[r0 + t4 + 4 + 8 * s];
                    ah[s][3] = qh32[r1 + t4 + 4 + 8 * s];
                    al[s][0] = ql32[r0 + t4 + 8 * s];
                    al[s][1] = ql32[r1 + t4 + 8 * s];
                    al[s][2] = ql32[r0 + t4 + 4 + 8 * s];
                    al[s][3] = ql32[r1 + t4 + 4 + 8 * s];
                }
            }
            if (t == TPI - 2 && tid == 0) *sm_next = atomicAdd(&g_ctr, 1u);
            if (t < TPI - 1) {
                prefetchKV(b, k0s + (t + 1) * 64, (tc + 1) & 1);
                asm volatile("cp.async.commit_group;" ::: "memory");
            } else {
                nwi = *sm_next;
                if (nwi < ITEMS) {
                    int nb = nwi / IPB, nr = nwi % IPB;
                    prefetchKV(nb, (nr % SPL) * 320, (tc + 1) & 1);
                    prefetchQ(nb, (nr / SPL) * 128);
                    asm volatile("cp.async.commit_group;" ::: "memory");
                }
            }

            const char* bb = smem + (tc & 1) * KBUF;
            const char* vb0 = bb + VOFF;

            // ---- j-pair pipeline: QK(jp+1) | exp/pack(jp) | PV(jp) ----
            float sc[2][2][4];
            u32 ph[4];

            #define QK_PAIR(jp, scp)                                            \
                do {                                                            \
                    (scp)[0][0] = -bd0; (scp)[0][1] = -bd0;                     \
                    (scp)[0][2] = -bd1; (scp)[0][3] = -bd1;                     \
                    (scp)[1][0] = -bd0; (scp)[1][1] = -bd0;                     \
                    (scp)[1][2] = -bd1; (scp)[1][3] = -bd1;                     \
                    _Pragma("unroll")                                           \
                    for (int jj = 0; jj < 2; jj++) {                            \
                        int j = 2 * (jp) + jj;                                  \
                        uint4 kk = *(const uint4*)(bb + ((8 * j + g) << 6) + (t4 << 4)); \
                        mma_f16((scp)[jj], ah[0], kk.x, kk.y);                  \
                        mma_f16((scp)[jj], al[0], kk.x, kk.y);                  \
                        mma_f16((scp)[jj], ah[1], kk.z, kk.w);                  \
                        mma_f16((scp)[jj], al[1], kk.z, kk.w);                  \
                    }                                                           \
                } while (0)

            QK_PAIR(0, sc[0]);
            #pragma unroll
            for (int jp = 0; jp < 4; jp++) {
                if (jp < 3) QK_PAIR(jp + 1, sc[(jp + 1) & 1]);

                float* s0 = sc[jp & 1][0];
                float* s1 = sc[jp & 1][1];
                float p0 = ex2f(s0[0]), p1 = ex2f(s0[1]);
                float p2 = ex2f(s0[2]), p3 = ex2f(s0[3]);
                float p4 = ex2f(s1[0]), p5 = ex2f(s1[1]);
                float p6 = ex2f(s1[2]), p7 = ex2f(s1[3]);
                ph[0] = pkbf(p1, p0); ph[1] = pkbf(p3, p2);
                ph[2] = pkbf(p5, p4); ph[3] = pkbf(p7, p6);
                l0 += bflo(ph[0]) + bfhi(ph[0]) + bflo(ph[2]) + bfhi(ph[2]);
                l1 += bflo(ph[1]) + bfhi(ph[1]) + bflo(ph[3]) + bfhi(ph[3]);

                const int so4 = (((jp ^ gp) << 2) + t4) << 4;
                #pragma unroll
                for (int j2 = 0; j2 < 4; j2++) {
                    uint4 vv = *(const uint4*)(vb0 + ((8 * j2 + g) << 8) + so4);
                    mma_bf16(o[j2], ph, vv.x, vv.y);   // Ph * Vh
                    mma_bf16(o[j2], ph, vv.z, vv.w);   // Ph * Vl
                }
            }
            #undef QK_PAIR
            tc++;
        }

        l0 += __shfl_xor_sync(0xffffffffu, l0, 1);
        l0 += __shfl_xor_sync(0xffffffffu, l0, 2);
        l1 += __shfl_xor_sync(0xffffffffu, l1, 1);
        l1 += __shfl_xor_sync(0xffffffffu, l1, 2);

        const int pb = (b * SPL + sp) * NP;
        #pragma unroll
        for (int j2 = 0; j2 < 4; j2++) {
            *(float2*)(g_acc + (pb + q0) * DI + 8 * j2 + 2 * t4) = make_float2(o[j2][0], o[j2][1]);
            *(float2*)(g_acc + (pb + q1) * DI + 8 * j2 + 2 * t4) = make_float2(o[j2][2], o[j2][3]);
        }
        if (t4 == 0) { g_lp[pb + q0] = l0; g_lp[pb + q1] = l1; }

        wi = nwi;
    }
}

// ---------------------------------------------------------------------------
// Stage 3: merge SPL partials + output projection + residual.
// ---------------------------------------------------------------------------
__global__ void __launch_bounds__(128) merge_kernel(
    const float* __restrict__ x,
    const float* __restrict__ w_w,
    float* __restrict__ out)
{
    __shared__ __align__(16) float ws[CH * DI];
    const int b = blockIdx.y, tid = threadIdx.x;
    const int n = blockIdx.x * 128 + tid;

    for (int i = tid; i < CH * DI; i += 128) ws[i] = w_w[i];
    __syncthreads();

    float l = 0.f;
    u64 y2[16];
    #pragma unroll
    for (int i = 0; i < 16; i++) y2[i] = 0ull;
    #pragma unroll 2
    for (int s = 0; s < SPL; s++) {
        l += g_lp[(b * SPL + s) * NP + n];
        const u64* ap = (const u64*)(g_acc + ((b * SPL + s) * NP + n) * DI);
        #pragma unroll
        for (int i2 = 0; i2 < 16; i2++) y2[i2] = f2add(y2[i2], ap[i2]);
    }
    const float inv = 1.f / l;
    u64 inv2; asm("mov.b64 %0,{%1,%1};" : "=l"(inv2) : "f"(inv));
    #pragma unroll
    for (int i2 = 0; i2 < 16; i2++) {
        u64 z = 0ull;
        y2[i2] = f2fma(y2[i2], inv2, z);
    }

    const float* xb = x + b * CH * NP + n;
    float* ob = out + b * CH * NP + n;
    #pragma unroll 2
    for (int c = 0; c < CH; c++) {
        const u64* w2 = (const u64*)(ws + c * DI);
        u64 o2 = 0ull;
        #pragma unroll
        for (int i2 = 0; i2 < 16; i2++) o2 = f2fma(w2[i2], y2[i2], o2);
        ob[c * NP] = xb[c * NP] + f2hadd(o2);
    }
}

// ---------------------------------------------------------------------------
extern "C" void kernel_launch(void* const* d_in, const int* in_sizes, int n_in,
                              void* d_out, int out_size)
{
    const float* x       = (const float*)d_in[0];
    const float* gw      = (const float*)d_in[1];
    const float* theta_w = (const float*)d_in[2];
    const float* phi_w   = (const float*)d_in[3];
    const float* w_w     = (const float*)d_in[4];
    float* out           = (float*)d_out;

    void* pm = nullptr; cudaGetSymbolAddress(&pm, g_phimax);
    cudaMemsetAsync(pm, 0, sizeof(unsigned) * BATCH);
    void* pc = nullptr; cudaGetSymbolAddress(&pc, g_ctr);
    cudaMemsetAsync(pc, 0, sizeof(unsigned));

    static int cfg = 0;
    if (!cfg) {
        cudaFuncSetAttribute(attn_kernel, cudaFuncAttributeMaxDynamicSharedMemorySize, ASMEM);
        cfg = 1;
    }

    dim3 gp(NP / PQ, 3, BATCH);
    proj_kernel<<<gp, 128>>>(x, theta_w, phi_w, gw);

    attn_kernel<<<304, 256, ASMEM>>>();

    dim3 gm(NP / 128, BATCH);
    merge_kernel<<<gm, 128>>>(x, w_w, out);
}

// round 16
// speedup vs baseline: 5.4855x; 1.1679x over previous
#include <cuda_runtime.h>
#include <cuda_bf16.h>
#include <cuda_fp16.h>
#include <cstdint>

#define BATCH 2
#define CH 64
#define DI 32
#define NP 6400
#define SPL 10
#define QTCH 100               // 64-key chunks per batch (g_Vz stride)
#define TPI 10                 // tiles per item (640 keys)
#define IPB 500                // items per batch = 50 qtiles * 10 splits
#define ITEMS 1000
#define LOG2E 1.4426950408889634f

typedef uint32_t u32;
typedef unsigned long long u64;

// ---------------- scratch ----------------
__device__ uint4 g_Qh[BATCH * NP * 4];   // fp16 q hi
__device__ uint4 g_Ql[BATCH * NP * 4];   // fp16 q lo residual
__device__ uint4 g_Kz[BATCH * NP * 4];   // fp16 k single, t4-blocked
__device__ uint4 g_Vz[BATCH * DI * QTCH * 16];  // bf16 hi/lo V^T blocks
__device__ float g_thn[BATCH * NP];
__device__ unsigned g_phimax[BATCH];
__device__ unsigned g_ctr;
__device__ float g_acc[BATCH * SPL * NP * DI];
__device__ float g_lp[BATCH * SPL * NP];

// ---------------- helpers ----------------
__device__ __forceinline__ u64 f2fma(u64 a, u64 b, u64 c) {
    u64 d; asm("fma.rn.f32x2 %0,%1,%2,%3;" : "=l"(d) : "l"(a), "l"(b), "l"(c)); return d;
}
__device__ __forceinline__ u64 f2add(u64 a, u64 b) {
    u64 d; asm("add.rn.f32x2 %0,%1,%2;" : "=l"(d) : "l"(a), "l"(b)); return d;
}
__device__ __forceinline__ float f2hadd(u64 a) {
    float lo, hi; asm("mov.b64 {%0,%1},%2;" : "=f"(lo), "=f"(hi) : "l"(a)); return lo + hi;
}
__device__ __forceinline__ u32 pkbf(float hi, float lo) {
    u32 r; asm("cvt.rn.bf16x2.f32 %0,%1,%2;" : "=r"(r) : "f"(hi), "f"(lo)); return r;
}
__device__ __forceinline__ u32 pkf16(float hi, float lo) {
    u32 r; asm("cvt.rn.f16x2.f32 %0,%1,%2;" : "=r"(r) : "f"(hi), "f"(lo)); return r;
}
__device__ __forceinline__ float f16lo(u32 p) {
    __half_raw hr; hr.x = (unsigned short)(p & 0xffffu); return __half2float(__half(hr));
}
__device__ __forceinline__ float f16hi(u32 p) {
    __half_raw hr; hr.x = (unsigned short)(p >> 16); return __half2float(__half(hr));
}
__device__ __forceinline__ float bflo(u32 p) { return __uint_as_float(p << 16); }
__device__ __forceinline__ float bfhi(u32 p) { return __uint_as_float(p & 0xffff0000u); }
__device__ __forceinline__ float ex2f(float x) {
    float r; asm("ex2.approx.f32 %0,%1;" : "=f"(r) : "f"(x)); return r;
}
__device__ __forceinline__ void mma_bf16(float* c, const u32* a, u32 b0, u32 b1) {
    asm("mma.sync.aligned.m16n8k16.row.col.f32.bf16.bf16.f32 "
        "{%0,%1,%2,%3},{%4,%5,%6,%7},{%8,%9},{%0,%1,%2,%3};"
        : "+f"(c[0]), "+f"(c[1]), "+f"(c[2]), "+f"(c[3])
        : "r"(a[0]), "r"(a[1]), "r"(a[2]), "r"(a[3]), "r"(b0), "r"(b1));
}
__device__ __forceinline__ void mma_f16(float* c, const u32* a, u32 b0, u32 b1) {
    asm("mma.sync.aligned.m16n8k16.row.col.f32.f16.f16.f32 "
        "{%0,%1,%2,%3},{%4,%5,%6,%7},{%8,%9},{%0,%1,%2,%3};"
        : "+f"(c[0]), "+f"(c[1]), "+f"(c[2]), "+f"(c[3])
        : "r"(a[0]), "r"(a[1]), "r"(a[2]), "r"(a[3]), "r"(b0), "r"(b1));
}
__device__ __forceinline__ void cpa16(u32 sa, const void* g) {
    asm volatile("cp.async.cg.shared.global [%0],[%1],16;" :: "r"(sa), "l"(g) : "memory");
}
__device__ __forceinline__ u32 smaddr(const void* p) {
    u32 a; asm("{ .reg .u64 t; cvta.to.shared.u64 t,%1; cvt.u32.u64 %0,t; }" : "=r"(a) : "l"(p));
    return a;
}

// ---------------------------------------------------------------------------
// Stage 1: projection (R13, unchanged). grid (100, 3, 2), 128 threads.
// ---------------------------------------------------------------------------
#define PQ 64
__global__ void __launch_bounds__(128) proj_kernel(
    const float* __restrict__ x,
    const float* __restrict__ theta_w,
    const float* __restrict__ phi_w,
    const float* __restrict__ gw)
{
    __shared__ __align__(16) float xs[CH * PQ];
    __shared__ __align__(16) float wT[CH * DI];

    const int b = blockIdx.z, m = blockIdx.y, n0 = blockIdx.x * PQ;
    const int tid = threadIdx.x;
    const int p = tid >> 1, h = tid & 1;
    const float* wsrc = (m == 0) ? theta_w : (m == 1) ? phi_w : gw;

    for (int idx = tid; idx < DI * CH; idx += 128) {
        int i = idx >> 6, c = idx & 63;
        wT[c * DI + i] = wsrc[idx];
    }
    const float* xb = x + b * CH * NP + n0;
    #pragma unroll
    for (int i = 0; i < 32; i++) {
        int idx = tid + 128 * i;
        xs[idx] = xb[(idx >> 6) * NP + (idx & 63)];
    }
    __syncthreads();

    u64 acc2[8];
    #pragma unroll
    for (int i = 0; i < 8; i++) acc2[i] = 0ull;
    #pragma unroll 4
    for (int c = 0; c < CH; c++) {
        float xv = xs[c * PQ + p];
        u64 x2; asm("mov.b64 %0,{%1,%1};" : "=l"(x2) : "f"(xv));
        const ulonglong2* w2 = (const ulonglong2*)(wT + c * DI + 16 * h);
        #pragma unroll
        for (int i4 = 0; i4 < 4; i4++) {
            ulonglong2 ww = w2[i4];
            acc2[2 * i4]     = f2fma(ww.x, x2, acc2[2 * i4]);
            acc2[2 * i4 + 1] = f2fma(ww.y, x2, acc2[2 * i4 + 1]);
        }
    }
    float v[16];
    #pragma unroll
    for (int i2 = 0; i2 < 8; i2++)
        asm("mov.b64 {%0,%1},%2;" : "=f"(v[2 * i2]), "=f"(v[2 * i2 + 1]) : "l"(acc2[i2]));

    const int n = n0 + p;
    if (m == 0) {
        #pragma unroll
        for (int i = 0; i < 16; i++) v[i] *= LOG2E;
        float nrm = 0.f;
        u32 hw[8], lw[8];
        #pragma unroll
        for (int i2 = 0; i2 < 8; i2++) {
            float f0 = v[2 * i2], f1 = v[2 * i2 + 1];
            nrm = fmaf(f0, f0, fmaf(f1, f1, nrm));
            u32 hh = pkf16(f1, f0);
            hw[i2] = hh;
            lw[i2] = pkf16(f1 - f16hi(hh), f0 - f16lo(hh));
        }
        nrm += __shfl_xor_sync(0xffffffffu, nrm, 1);
        uint4* hp = g_Qh + (b * NP + n) * 4 + 2 * h;
        uint4* lp = g_Ql + (b * NP + n) * 4 + 2 * h;
        hp[0] = make_uint4(hw[0], hw[1], hw[2], hw[3]);
        hp[1] = make_uint4(hw[4], hw[5], hw[6], hw[7]);
        lp[0] = make_uint4(lw[0], lw[1], lw[2], lw[3]);
        lp[1] = make_uint4(lw[4], lw[5], lw[6], lw[7]);
        if (h == 0) g_thn[b * NP + n] = nrm;
    } else if (m == 1) {
        float nrm = 0.f;
        u32 kw[8];
        #pragma unroll
        for (int i2 = 0; i2 < 8; i2++) {
            float f0 = v[2 * i2], f1 = v[2 * i2 + 1];
            nrm = fmaf(f0, f0, fmaf(f1, f1, nrm));
            kw[i2] = pkf16(f1, f0);
        }
        nrm += __shfl_xor_sync(0xffffffffu, nrm, 1);
        u32 ok[8];
        #pragma unroll
        for (int t = 0; t < 8; t++)
            ok[t] = __shfl_xor_sync(0xffffffffu, kw[t], 1);
        uint4* dst = g_Kz + (b * NP + n) * 4;
        if (h == 0) {
            dst[0] = make_uint4(kw[0], kw[4], ok[0], ok[4]);
            dst[1] = make_uint4(kw[1], kw[5], ok[1], ok[5]);
        } else {
            dst[2] = make_uint4(ok[2], ok[6], kw[2], kw[6]);
            dst[3] = make_uint4(ok[3], ok[7], kw[3], kw[7]);
        }
        unsigned mx = __reduce_max_sync(0xffffffffu, __float_as_uint(nrm));
        if ((tid & 31) == 0) atomicMax(&g_phimax[b], mx);
    } else {
        __syncthreads();
        u32* vh = (u32*)xs;
        u32* vl = vh + 32 * 32;
        __nv_bfloat16* vhb = (__nv_bfloat16*)vh;
        __nv_bfloat16* vlb = (__nv_bfloat16*)vl;
        #pragma unroll
        for (int i = 0; i < 16; i++) {
            int d = 16 * h + i;
            __nv_bfloat16 hh = __float2bfloat16(v[i]);
            vhb[d * PQ + p] = hh;
            vlb[d * PQ + p] = __float2bfloat16(v[i] - __bfloat162float(hh));
        }
        __syncthreads();
        #pragma unroll
        for (int i = 0; i < 4; i++) {
            int idx = tid + 128 * i;
            int d = idx >> 4, rem = idx & 15;
            int s4 = rem >> 2, t4 = rem & 3;
            int kp = 8 * s4 + t4;
            uint4 val = make_uint4(vh[d * 32 + kp], vh[d * 32 + kp + 4],
                                   vl[d * 32 + kp], vl[d * 32 + kp + 4]);
            int blk = ((s4 ^ (d & 1)) << 2) + t4;
            g_Vz[((b * DI + d) * QTCH + blockIdx.x) * 16 + blk] = val;
        }
    }
}

// ---------------------------------------------------------------------------
// Stage 2: persistent flash attention (R13 config: SPL=10, TPI=10, 296 CTAs).
// QK = fp16 2-term (32 MMA), PV = bf16 2-term (32 MMA). 64 slots/warp-tile.
// ---------------------------------------------------------------------------
#define KBUF 12288
#define VOFF 4096
#define QOFF 24576
#define SMN  40960
#define ASMEM 40976

__global__ void __launch_bounds__(256, 2) attn_kernel()
{
    extern __shared__ __align__(16) char smem[];
    const int tid = threadIdx.x, w = tid >> 5, lane = tid & 31;
    const int g = lane >> 2, t4 = lane & 3;
    const int gp = g & 1;
    const u32 smbase = smaddr(smem);
    volatile u32* sm_next = (volatile u32*)(smem + SMN);

    auto prefetchKV = [&](int b, int k0, int buf) {
        const u32 bb = smbase + buf * KBUF;
        const uint4* ks = g_Kz + (b * NP + k0) * 4;           // 256 uint4
        const uint4* vs = g_Vz + (b * DI * QTCH + (k0 >> 6)) * 16;
        cpa16(bb + tid * 16, ks + tid);
        #pragma unroll
        for (int i = 0; i < 2; i++) {
            int idx = tid + 256 * i;
            int d = idx >> 4, blk = idx & 15;
            cpa16(bb + VOFF + idx * 16, vs + d * QTCH * 16 + blk);
        }
    };
    auto prefetchQ = [&](int b, int n0) {
        const uint4* qh = g_Qh + (b * NP + n0) * 4;           // 512 uint4
        const uint4* ql = g_Ql + (b * NP + n0) * 4;
        #pragma unroll
        for (int i = 0; i < 2; i++) {
            int idx = tid + 256 * i;
            cpa16(smbase + QOFF + idx * 16, qh + idx);
            cpa16(smbase + QOFF + 8192 + idx * 16, ql + idx);
        }
    };

    if (tid == 0) *sm_next = atomicAdd(&g_ctr, 1u);
    __syncthreads();
    unsigned wi = *sm_next;
    if (wi < ITEMS) {
        int b = wi / IPB, r = wi % IPB;
        prefetchKV(b, (r % SPL) * 640, 0);
        prefetchQ(b, (r / SPL) * 128);
        asm volatile("cp.async.commit_group;" ::: "memory");
    }
    int tc = 0;

    while (wi < ITEMS) {
        const int b = wi / IPB;
        const int r = wi % IPB;
        const int qt = r / SPL, sp = r % SPL;
        const int n0 = qt * 128, k0s = sp * 640;
        const int lr0 = w * 16 + g;
        const int q0 = n0 + lr0, q1 = q0 + 8;

        const float pm = sqrtf(__uint_as_float(g_phimax[b]));
        const float bd0 = sqrtf(g_thn[b * NP + q0]) * pm;
        const float bd1 = sqrtf(g_thn[b * NP + q1]) * pm;

        float o[4][4];
        #pragma unroll
        for (int i = 0; i < 4; i++)
            #pragma unroll
            for (int j = 0; j < 4; j++) o[i][j] = 0.f;
        float l0 = 0.f, l1 = 0.f;
        u32 ah[2][4], al[2][4];
        unsigned nwi = ITEMS;

        for (int t = 0; t < TPI; t++) {
            asm volatile("cp.async.wait_group 0;" ::: "memory");
            __syncthreads();

            if (t == 0) {
                const u32* qh32 = (const u32*)(smem + QOFF);
                const u32* ql32 = (const u32*)(smem + QOFF + 8192);
                const int r0 = lr0 * 16, r1 = (lr0 + 8) * 16;
                #pragma unroll
                for (int s = 0; s < 2; s++) {
                    ah[s][0] = qh32[r0 + t4 + 8 * s];
                    ah[s][1] = qh32[r1 + t4 + 8 * s];
                    ah[s][2] = qh32[r0 + t4 + 4 + 8 * s];
                    ah[s][3] = qh32[r1 + t4 + 4 + 8 * s];
                    al[s][0] = ql32[r0 + t4 + 8 * s];
                    al[s][1] = ql32[r1 + t4 + 8 * s];
                    al[s][2] = ql32[r0 + t4 + 4 + 8 * s];
                    al[s][3] = ql32[r1 + t4 + 4 + 8 * s];
                }
            }
            if (t == TPI - 2 && tid == 0) *sm_next = atomicAdd(&g_ctr, 1u);
            if (t < TPI - 1) {
                prefetchKV(b, k0s + (t + 1) * 64, (tc + 1) & 1);
                asm volatile("cp.async.commit_group;" ::: "memory");
            } else {
                nwi = *sm_next;
                if (nwi < ITEMS) {
                    int nb = nwi / IPB, nr = nwi % IPB;
                    prefetchKV(nb, (nr % SPL) * 640, (tc + 1) & 1);
                    prefetchQ(nb, (nr / SPL) * 128);
                    asm volatile("cp.async.commit_group;" ::: "memory");
                }
            }

            const char* bb = smem + (tc & 1) * KBUF;
            const char* vb0 = bb + VOFF;

            // ---- j-pair pipeline: QK(jp+1) | exp/pack(jp) | PV(jp) ----
            float sc[2][2][4];
            u32 ph[4];

            #define QK_PAIR(jp, scp)                                            \
                do {                                                            \
                    (scp)[0][0] = -bd0; (scp)[0][1] = -bd0;                     \
                    (scp)[0][2] = -bd1; (scp)[0][3] = -bd1;                     \
                    (scp)[1][0] = -bd0; (scp)[1][1] = -bd0;                     \
                    (scp)[1][2] = -bd1; (scp)[1][3] = -bd1;                     \
                    _Pragma("unroll")                                           \
                    for (int jj = 0; jj < 2; jj++) {                            \
                        int j = 2 * (jp) + jj;                                  \
                        uint4 kk = *(const uint4*)(bb + ((8 * j + g) << 6) + (t4 << 4)); \
                        mma_f16((scp)[jj], ah[0], kk.x, kk.y);                  \
                        mma_f16((scp)[jj], al[0], kk.x, kk.y);                  \
                        mma_f16((scp)[jj], ah[1], kk.z, kk.w);                  \
                        mma_f16((scp)[jj], al[1], kk.z, kk.w);                  \
                    }                                                           \
                } while (0)

            QK_PAIR(0, sc[0]);
            #pragma unroll
            for (int jp = 0; jp < 4; jp++) {
                if (jp < 3) QK_PAIR(jp + 1, sc[(jp + 1) & 1]);

                float* s0 = sc[jp & 1][0];
                float* s1 = sc[jp & 1][1];
                float p0 = ex2f(s0[0]), p1 = ex2f(s0[1]);
                float p2 = ex2f(s0[2]), p3 = ex2f(s0[3]);
                float p4 = ex2f(s1[0]), p5 = ex2f(s1[1]);
                float p6 = ex2f(s1[2]), p7 = ex2f(s1[3]);
                ph[0] = pkbf(p1, p0); ph[1] = pkbf(p3, p2);
                ph[2] = pkbf(p5, p4); ph[3] = pkbf(p7, p6);
                l0 += bflo(ph[0]) + bfhi(ph[0]) + bflo(ph[2]) + bfhi(ph[2]);
                l1 += bflo(ph[1]) + bfhi(ph[1]) + bflo(ph[3]) + bfhi(ph[3]);

                const int so4 = (((jp ^ gp) << 2) + t4) << 4;
                #pragma unroll
                for (int j2 = 0; j2 < 4; j2++) {
                    uint4 vv = *(const uint4*)(vb0 + ((8 * j2 + g) << 8) + so4);
                    mma_bf16(o[j2], ph, vv.x, vv.y);   // Ph * Vh
                    mma_bf16(o[j2], ph, vv.z, vv.w);   // Ph * Vl
                }
            }
            #undef QK_PAIR
            tc++;
        }

        l0 += __shfl_xor_sync(0xffffffffu, l0, 1);
        l0 += __shfl_xor_sync(0xffffffffu, l0, 2);
        l1 += __shfl_xor_sync(0xffffffffu, l1, 1);
        l1 += __shfl_xor_sync(0xffffffffu, l1, 2);

        const int pb = (b * SPL + sp) * NP;
        #pragma unroll
        for (int j2 = 0; j2 < 4; j2++) {
            *(float2*)(g_acc + (pb + q0) * DI + 8 * j2 + 2 * t4) = make_float2(o[j2][0], o[j2][1]);
            *(float2*)(g_acc + (pb + q1) * DI + 8 * j2 + 2 * t4) = make_float2(o[j2][2], o[j2][3]);
        }
        if (t4 == 0) { g_lp[pb + q0] = l0; g_lp[pb + q1] = l1; }

        wi = nwi;
    }
}

// ---------------------------------------------------------------------------
// Stage 3: merge SPL partials + output projection + residual.
// Also resets g_ctr / g_phimax for the next graph replay (no memsets needed).
// ---------------------------------------------------------------------------
__global__ void __launch_bounds__(128) merge_kernel(
    const float* __restrict__ x,
    const float* __restrict__ w_w,
    float* __restrict__ out)
{
    __shared__ __align__(16) float ws[CH * DI];
    const int b = blockIdx.y, tid = threadIdx.x;
    const int n = blockIdx.x * 128 + tid;

    if (blockIdx.x == 0 && blockIdx.y == 0 && tid < 4) {
        if (tid == 0) g_ctr = 0u;
        if (tid < BATCH + 1 && tid >= 1) g_phimax[tid - 1] = 0u;
    }

    for (int i = tid; i < CH * DI; i += 128) ws[i] = w_w[i];
    __syncthreads();

    float l = 0.f;
    u64 y2[16];
    #pragma unroll
    for (int i = 0; i < 16; i++) y2[i] = 0ull;
    #pragma unroll 2
    for (int s = 0; s < SPL; s++) {
        l += g_lp[(b * SPL + s) * NP + n];
        const u64* ap = (const u64*)(g_acc + ((b * SPL + s) * NP + n) * DI);
        #pragma unroll
        for (int i2 = 0; i2 < 16; i2++) y2[i2] = f2add(y2[i2], ap[i2]);
    }
    const float inv = 1.f / l;
    u64 inv2; asm("mov.b64 %0,{%1,%1};" : "=l"(inv2) : "f"(inv));
    #pragma unroll
    for (int i2 = 0; i2 < 16; i2++) {
        u64 z = 0ull;
        y2[i2] = f2fma(y2[i2], inv2, z);
    }

    const float* xb = x + b * CH * NP + n;
    float* ob = out + b * CH * NP + n;
    #pragma unroll 2
    for (int c = 0; c < CH; c++) {
        const u64* w2 = (const u64*)(ws + c * DI);
        u64 o2 = 0ull;
        #pragma unroll
        for (int i2 = 0; i2 < 16; i2++) o2 = f2fma(w2[i2], y2[i2], o2);
        ob[c * NP] = xb[c * NP] + f2hadd(o2);
    }
}

// dummy 4th launch: pads the per-iteration kernel count so ncu -s 5 -c 1
// captures attn_kernel (launch index 5 = iter-2 attn).
__global__ void pad_kernel() {}

// ---------------------------------------------------------------------------
extern "C" void kernel_launch(void* const* d_in, const int* in_sizes, int n_in,
                              void* d_out, int out_size)
{
    const float* x       = (const float*)d_in[0];
    const float* gw      = (const float*)d_in[1];
    const float* theta_w = (const float*)d_in[2];
    const float* phi_w   = (const float*)d_in[3];
    const float* w_w     = (const float*)d_in[4];
    float* out           = (float*)d_out;

    static int cfg = 0;
    if (!cfg) {
        cudaFuncSetAttribute(attn_kernel, cudaFuncAttributeMaxDynamicSharedMemorySize, ASMEM);
        cfg = 1;
    }

    dim3 gp(NP / PQ, 3, BATCH);
    proj_kernel<<<gp, 128>>>(x, theta_w, phi_w, gw);

    attn_kernel<<<296, 256, ASMEM>>>();

    dim3 gm(NP / 128, BATCH);
    merge_kernel<<<gm, 128>>>(x, w_w, out);

    pad_kernel<<<1, 32>>>();
}